// round 9
// baseline (speedup 1.0000x reference)
#include <cuda_runtime.h>
#include <cuda_fp16.h>
#include <cstdint>

// Problem constants (B=2, S=2048, D=1024, E=8, I=1408, TOPK=2)
#define TTOK 4096
#define DDIM 1024
#define ENUM 8
#define IDIM 1408

#define BKH 64        // K per tile in halves = 128 bytes/row
#define KSTEPS 4      // k16 steps per tile

// ---------------- static device scratch (no allocations allowed) ----------------
__device__ int    g_cnt[ENUM];
__device__ int    g_tok[ENUM * TTOK];
__device__ int    g_slot[ENUM * TTOK];
__device__ float  g_prob[ENUM * TTOK];
__device__ __half g_xh[(size_t)TTOK * DDIM];
__device__ __half g_wgh[(size_t)ENUM * IDIM * DDIM];
__device__ __half g_wuh[(size_t)ENUM * IDIM * DDIM];
__device__ __half g_wdh[(size_t)ENUM * DDIM * IDIM];
__device__ __half g_h[(size_t)ENUM * TTOK * IDIM];

// ---------------- helpers ----------------
__device__ __forceinline__ uint32_t smem_u32(const void* p) {
    return (uint32_t)__cvta_generic_to_shared(p);
}

__device__ __forceinline__ void mma16816(float* c, const uint32_t* a, uint32_t b0, uint32_t b1) {
    asm volatile(
        "mma.sync.aligned.m16n8k16.row.col.f32.f16.f16.f32 "
        "{%0,%1,%2,%3},{%4,%5,%6,%7},{%8,%9},{%0,%1,%2,%3};\n"
        : "+f"(c[0]), "+f"(c[1]), "+f"(c[2]), "+f"(c[3])
        : "r"(a[0]), "r"(a[1]), "r"(a[2]), "r"(a[3]), "r"(b0), "r"(b1));
}

__device__ __forceinline__ void ldsm_x4(uint32_t* r, uint32_t addr) {
    asm volatile("ldmatrix.sync.aligned.m8n8.x4.shared.b16 {%0,%1,%2,%3}, [%4];"
                 : "=r"(r[0]), "=r"(r[1]), "=r"(r[2]), "=r"(r[3]) : "r"(addr));
}

__device__ __forceinline__ void cpa16(uint32_t saddr, const void* g) {
    asm volatile("cp.async.cg.shared.global [%0], [%1], 16;\n" :: "r"(saddr), "l"(g));
}
__device__ __forceinline__ void cpa_commit() { asm volatile("cp.async.commit_group;\n"); }
template <int N>
__device__ __forceinline__ void cpa_wait() { asm volatile("cp.async.wait_group %0;\n" :: "n"(N)); }

__device__ __forceinline__ void red_add_f32(float* p, float v) {
    asm volatile("red.global.add.f32 [%0], %1;" :: "l"(p), "f"(v) : "memory");
}

// ---------------- kernel: zero expert counters (critical path, tiny) ----------------
__global__ void k_zero_cnt() {
    if (threadIdx.x < ENUM) g_cnt[threadIdx.x] = 0;
}

// ---------------- kernel: zero d_out (off critical path, on s2) ----------------
__global__ void k_zero_dout(float4* __restrict__ out) {
    int i = blockIdx.x * blockDim.x + threadIdx.x;
    out[i] = make_float4(0.f, 0.f, 0.f, 0.f);
}

// ---------------- kernels: fp32 -> fp16 convert ----------------
__global__ void k_cvt_gu(const float4* __restrict__ s0, const float4* __restrict__ s1,
                         __half2* __restrict__ d0, __half2* __restrict__ d1, int n4) {
    const float4* src = (blockIdx.y == 0) ? s0 : s1;
    __half2* dst = (blockIdx.y == 0) ? d0 : d1;
    int i = blockIdx.x * (blockDim.x * 2) + threadIdx.x;
    int j = i + blockDim.x;
    float4 v0 = src[i];
    float4 v1 = (j < n4) ? src[j] : make_float4(0.f, 0.f, 0.f, 0.f);
    dst[i * 2]     = __floats2half2_rn(v0.x, v0.y);
    dst[i * 2 + 1] = __floats2half2_rn(v0.z, v0.w);
    if (j < n4) {
        dst[j * 2]     = __floats2half2_rn(v1.x, v1.y);
        dst[j * 2 + 1] = __floats2half2_rn(v1.z, v1.w);
    }
}

__global__ void k_cvt_one(const float4* __restrict__ src, __half2* __restrict__ dst, int n4) {
    int i = blockIdx.x * (blockDim.x * 2) + threadIdx.x;
    int j = i + blockDim.x;
    float4 v0 = src[i];
    float4 v1 = (j < n4) ? src[j] : make_float4(0.f, 0.f, 0.f, 0.f);
    dst[i * 2]     = __floats2half2_rn(v0.x, v0.y);
    dst[i * 2 + 1] = __floats2half2_rn(v0.z, v0.w);
    if (j < n4) {
        dst[j * 2]     = __floats2half2_rn(v1.x, v1.y);
        dst[j * 2 + 1] = __floats2half2_rn(v1.z, v1.w);
    }
}

// ---------------- kernel 1: router (gate_w staged in smem) ----------------
__global__ __launch_bounds__(256) void k_router(const float* __restrict__ x,
                                                const float* __restrict__ gw) {
    __shared__ float4 sGw[ENUM * DDIM / 4];   // 32 KB

    const int tid = threadIdx.x;
#pragma unroll
    for (int i = 0; i < ENUM * DDIM / 4 / 256; i++)
        sGw[tid + i * 256] = ((const float4*)gw)[tid + i * 256];
    __syncthreads();

    const int wid = tid >> 5;
    const int lane = tid & 31;
    const int tok = blockIdx.x * 8 + wid;

    const float4* xr = (const float4*)(x + (size_t)tok * DDIM);
    __half2* xh2 = (__half2*)(g_xh + (size_t)tok * DDIM);

    float acc[ENUM];
#pragma unroll
    for (int e = 0; e < ENUM; e++) acc[e] = 0.f;

#pragma unroll
    for (int it = 0; it < DDIM / 4 / 32; it++) {
        int c = lane + it * 32;
        float4 xv = xr[c];
        xh2[c * 2]     = __floats2half2_rn(xv.x, xv.y);
        xh2[c * 2 + 1] = __floats2half2_rn(xv.z, xv.w);
#pragma unroll
        for (int e = 0; e < ENUM; e++) {
            float4 wv = sGw[e * (DDIM / 4) + c];
            acc[e] += xv.x * wv.x + xv.y * wv.y + xv.z * wv.z + xv.w * wv.w;
        }
    }
#pragma unroll
    for (int e = 0; e < ENUM; e++) {
#pragma unroll
        for (int off = 16; off > 0; off >>= 1)
            acc[e] += __shfl_xor_sync(0xFFFFFFFFu, acc[e], off);
    }

    if (lane == 0) {
        int i0 = 0;
        float s0 = acc[0];
#pragma unroll
        for (int e = 1; e < ENUM; e++)
            if (acc[e] > s0) { s0 = acc[e]; i0 = e; }
        int i1 = -1;
        float s1 = -3.4e38f;
#pragma unroll
        for (int e = 0; e < ENUM; e++)
            if (e != i0 && acc[e] > s1) { s1 = acc[e]; i1 = e; }

        float e1 = expf(s1 - s0);
        float inv = 1.f / (1.f + e1);

        int pos0 = atomicAdd(&g_cnt[i0], 1);
        g_tok[i0 * TTOK + pos0]  = tok;
        g_slot[i0 * TTOK + pos0] = 0;
        g_prob[i0 * TTOK + pos0] = inv;

        int pos1 = atomicAdd(&g_cnt[i1], 1);
        g_tok[i1 * TTOK + pos1]  = tok;
        g_slot[i1 * TTOK + pos1] = 1;
        g_prob[i1 * TTOK + pos1] = e1 * inv;
    }
}

// =====================================================================
// kernel 2: ffn1 — fp16 mma: [128 gathered tokens] x [64 I-cols], G & U,
//           fused silu(g)*u*prob -> g_h (fp16). 3-stage cp.async pipeline
//           + register-fragment software pipelining. ebase = expert group.
// =====================================================================
#define F1_GOFF 16384
#define F1_UOFF 24576
#define F1_STG  32768
#define F1_KT   (DDIM / BKH)   // 16
#define F1_SMEM (3 * F1_STG + 256)

__global__ __launch_bounds__(256, 2) void k_ffn1(int ebase) {
    __shared__ int   sTok[128];
    __shared__ float sProb[128];
    extern __shared__ char dynsm[];

    uint32_t raw = smem_u32(dynsm);
    uint32_t sbase = (raw + 127) & ~127u;

    const int e = ebase + blockIdx.z;
    const int cnt = g_cnt[e];
    const int m0 = blockIdx.y * 128;
    if (m0 >= cnt) return;
    const int n0 = blockIdx.x * 64;
    const int tid = threadIdx.x;

    if (tid < 128) {
        int rc = min(m0 + tid, cnt - 1);
        sTok[tid]  = g_tok[e * TTOK + rc];
        sProb[tid] = g_prob[e * TTOK + rc];
    }
    __syncthreads();

    const int lane = tid & 31;
    const int wid = tid >> 5;
    const int wm0 = (wid & 3) * 32;
    const int wn0 = (wid >> 2) * 32;
    const int sub = lane >> 3;
    const int l8 = lane & 7;

    const __half* wgb = g_wgh + (size_t)e * IDIM * DDIM;
    const __half* wub = g_wuh + (size_t)e * IDIM * DDIM;

    const __half* aSrc[4];
    uint32_t aDst[4];
#pragma unroll
    for (int i = 0; i < 4; i++) {
        int f = tid + i * 256;
        int row = f >> 3, c = f & 7;
        aDst[i] = row * 128 + ((c ^ (row & 7)) << 4);
        aSrc[i] = g_xh + (size_t)sTok[row] * DDIM + c * 8;
    }
    const __half* gSrc[2];
    const __half* uSrc[2];
    uint32_t wDst[2];
#pragma unroll
    for (int i = 0; i < 2; i++) {
        int f = tid + i * 256;
        int row = f >> 3, c = f & 7;
        wDst[i] = row * 128 + ((c ^ (row & 7)) << 4);
        gSrc[i] = wgb + (size_t)(n0 + row) * DDIM + c * 8;
        uSrc[i] = wub + (size_t)(n0 + row) * DDIM + c * 8;
    }

    auto load_stage = [&](int st, int kt) {
        uint32_t b = sbase + st * F1_STG;
        int kb = kt * BKH;
#pragma unroll
        for (int i = 0; i < 4; i++) cpa16(b + aDst[i], aSrc[i] + kb);
#pragma unroll
        for (int i = 0; i < 2; i++) {
            cpa16(b + F1_GOFF + wDst[i], gSrc[i] + kb);
            cpa16(b + F1_UOFF + wDst[i], uSrc[i] + kb);
        }
    };

    uint32_t aRow[2], aXor[2];
#pragma unroll
    for (int mt = 0; mt < 2; mt++) {
        int row = wm0 + mt * 16 + ((sub & 1) << 3) + l8;
        aRow[mt] = row * 128;
        aXor[mt] = row & 7;
    }
    const uint32_t aBit = sub >> 1;
    uint32_t bRow[2], bXor[2];
#pragma unroll
    for (int p = 0; p < 2; p++) {
        int row = wn0 + p * 16 + ((sub >> 1) << 3) + l8;
        bRow[p] = row * 128;
        bXor[p] = row & 7;
    }
    const uint32_t bBit = sub & 1;

    float cg[2][4][4], cu[2][4][4];
#pragma unroll
    for (int a = 0; a < 2; a++)
#pragma unroll
        for (int b = 0; b < 4; b++)
#pragma unroll
            for (int c = 0; c < 4; c++) { cg[a][b][c] = 0.f; cu[a][b][c] = 0.f; }

    load_stage(0, 0);
    cpa_commit();
    load_stage(1, 1);
    cpa_commit();

    for (int kt = 0; kt < F1_KT; kt++) {
        cpa_wait<1>();
        __syncthreads();
        if (kt + 2 < F1_KT) {
            int st = (kt + 2) % 3;
            load_stage(st, kt + 2);
        }
        cpa_commit();

        uint32_t stA = sbase + (kt % 3) * F1_STG;
        uint32_t stG = stA + F1_GOFF;
        uint32_t stU = stA + F1_UOFF;

        uint32_t aF[2][2][4];
        uint32_t bgF[2][4], buF[2][4];
        ldsm_x4(aF[0][0], stA + aRow[0] + ((aBit ^ aXor[0]) << 4));
        ldsm_x4(aF[0][1], stA + aRow[1] + ((aBit ^ aXor[1]) << 4));
        ldsm_x4(bgF[0], stG + bRow[0] + ((bBit ^ bXor[0]) << 4));
        ldsm_x4(buF[0], stU + bRow[0] + ((bBit ^ bXor[0]) << 4));
#pragma unroll
        for (int g = 0; g < 2 * KSTEPS; g++) {
            const int ks = g >> 1, p = g & 1;
            const int gn = g + 1;
            if (gn < 2 * KSTEPS) {
                const int nks = gn >> 1, np = gn & 1;
                if (np == 0) {
                    uint32_t ca = (uint32_t)(nks * 2) + aBit;
                    ldsm_x4(aF[nks & 1][0], stA + aRow[0] + ((ca ^ aXor[0]) << 4));
                    ldsm_x4(aF[nks & 1][1], stA + aRow[1] + ((ca ^ aXor[1]) << 4));
                }
                uint32_t cb = (uint32_t)(nks * 2) + bBit;
                ldsm_x4(bgF[gn & 1], stG + bRow[np] + ((cb ^ bXor[np]) << 4));
                ldsm_x4(buF[gn & 1], stU + bRow[np] + ((cb ^ bXor[np]) << 4));
            }
            const uint32_t* a0 = aF[ks & 1][0];
            const uint32_t* a1 = aF[ks & 1][1];
            const uint32_t* bg = bgF[g & 1];
            const uint32_t* bu = buF[g & 1];
            mma16816(cg[0][p * 2],     a0, bg[0], bg[1]);
            mma16816(cg[0][p * 2 + 1], a0, bg[2], bg[3]);
            mma16816(cu[0][p * 2],     a0, bu[0], bu[1]);
            mma16816(cu[0][p * 2 + 1], a0, bu[2], bu[3]);
            mma16816(cg[1][p * 2],     a1, bg[0], bg[1]);
            mma16816(cg[1][p * 2 + 1], a1, bg[2], bg[3]);
            mma16816(cu[1][p * 2],     a1, bu[0], bu[1]);
            mma16816(cu[1][p * 2 + 1], a1, bu[2], bu[3]);
        }
    }

    __half* hb = g_h + (size_t)e * TTOK * IDIM;
#pragma unroll
    for (int mt = 0; mt < 2; mt++) {
#pragma unroll
        for (int nt = 0; nt < 4; nt++) {
            int colp = n0 + wn0 + nt * 8 + 2 * (lane & 3);
#pragma unroll
            for (int half = 0; half < 2; half++) {
                int rl = wm0 + mt * 16 + (lane >> 2) + half * 8;
                if (m0 + rl < cnt) {
                    float g0 = cg[mt][nt][half * 2], g1 = cg[mt][nt][half * 2 + 1];
                    float u0 = cu[mt][nt][half * 2], u1 = cu[mt][nt][half * 2 + 1];
                    float p = sProb[rl];
                    float h0 = (g0 / (1.f + __expf(-g0))) * u0 * p;
                    float h1 = (g1 / (1.f + __expf(-g1))) * u1 * p;
                    *(__half2*)(hb + (size_t)(m0 + rl) * IDIM + colp) = __floats2half2_rn(h0, h1);
                }
            }
        }
    }
}

// =====================================================================
// kernel 3: ffn2 — fp16 mma: [128 slot rows] x [128 D-cols], K=1408
//           3-stage cp.async pipeline + register-fragment pipelining;
//           red.add directly into d_out. ebase = expert group.
// =====================================================================
#define F2_BOFF 16384
#define F2_STG  32768
#define F2_KT   (IDIM / BKH)   // 22
#define F2_SMEM (3 * F2_STG + 256)

__global__ __launch_bounds__(256, 2) void k_ffn2(float* __restrict__ out, int ebase) {
    __shared__ int sTok[128];
    extern __shared__ char dynsm[];

    uint32_t raw = smem_u32(dynsm);
    uint32_t sbase = (raw + 127) & ~127u;

    const int e = ebase + blockIdx.z;
    const int cnt = g_cnt[e];
    const int m0 = blockIdx.y * 128;
    if (m0 >= cnt) return;
    const int n0 = blockIdx.x * 128;
    const int tid = threadIdx.x;

    if (tid < 128) {
        int rc = min(m0 + tid, cnt - 1);
        sTok[tid] = g_tok[e * TTOK + rc];
    }
    __syncthreads();

    const int lane = tid & 31;
    const int wid = tid >> 5;
    const int wm0 = (wid & 3) * 32;
    const int wn0 = (wid >> 2) * 64;
    const int sub = lane >> 3;
    const int l8 = lane & 7;

    const __half* hb  = g_h + (size_t)e * TTOK * IDIM;
    const __half* wdb = g_wdh + (size_t)e * DDIM * IDIM;

    const __half* aSrc[4];
    const __half* bSrc[4];
    uint32_t tDst[4];
#pragma unroll
    for (int i = 0; i < 4; i++) {
        int f = tid + i * 256;
        int row = f >> 3, c = f & 7;
        tDst[i] = row * 128 + ((c ^ (row & 7)) << 4);
        int rc = min(m0 + row, cnt - 1);
        aSrc[i] = hb + (size_t)rc * IDIM + c * 8;
        bSrc[i] = wdb + (size_t)(n0 + row) * IDIM + c * 8;
    }

    auto load_stage = [&](int st, int kt) {
        uint32_t b = sbase + st * F2_STG;
        int kb = kt * BKH;
#pragma unroll
        for (int i = 0; i < 4; i++) {
            cpa16(b + tDst[i], aSrc[i] + kb);
            cpa16(b + F2_BOFF + tDst[i], bSrc[i] + kb);
        }
    };

    uint32_t aRow[2], aXor[2];
#pragma unroll
    for (int mt = 0; mt < 2; mt++) {
        int row = wm0 + mt * 16 + ((sub & 1) << 3) + l8;
        aRow[mt] = row * 128;
        aXor[mt] = row & 7;
    }
    const uint32_t aBit = sub >> 1;
    uint32_t bRow[4], bXor[4];
#pragma unroll
    for (int p = 0; p < 4; p++) {
        int row = wn0 + p * 16 + ((sub >> 1) << 3) + l8;
        bRow[p] = row * 128;
        bXor[p] = row & 7;
    }
    const uint32_t bBit = sub & 1;

    float cc[2][8][4];
#pragma unroll
    for (int a = 0; a < 2; a++)
#pragma unroll
        for (int b = 0; b < 8; b++)
#pragma unroll
            for (int c = 0; c < 4; c++) cc[a][b][c] = 0.f;

    load_stage(0, 0);
    cpa_commit();
    load_stage(1, 1);
    cpa_commit();

    for (int kt = 0; kt < F2_KT; kt++) {
        cpa_wait<1>();
        __syncthreads();
        if (kt + 2 < F2_KT) {
            int st = (kt + 2) % 3;
            load_stage(st, kt + 2);
        }
        cpa_commit();

        uint32_t stA = sbase + (kt % 3) * F2_STG;
        uint32_t stB = stA + F2_BOFF;

        uint32_t aF[2][2][4];
        uint32_t bbF[2][4];
        ldsm_x4(aF[0][0], stA + aRow[0] + ((aBit ^ aXor[0]) << 4));
        ldsm_x4(aF[0][1], stA + aRow[1] + ((aBit ^ aXor[1]) << 4));
        ldsm_x4(bbF[0], stB + bRow[0] + ((bBit ^ bXor[0]) << 4));
#pragma unroll
        for (int g = 0; g < 4 * KSTEPS; g++) {
            const int ks = g >> 2, p = g & 3;
            const int gn = g + 1;
            if (gn < 4 * KSTEPS) {
                const int nks = gn >> 2, np = gn & 3;
                if (np == 0) {
                    uint32_t ca = (uint32_t)(nks * 2) + aBit;
                    ldsm_x4(aF[nks & 1][0], stA + aRow[0] + ((ca ^ aXor[0]) << 4));
                    ldsm_x4(aF[nks & 1][1], stA + aRow[1] + ((ca ^ aXor[1]) << 4));
                }
                uint32_t cb = (uint32_t)(nks * 2) + bBit;
                ldsm_x4(bbF[gn & 1], stB + bRow[np] + ((cb ^ bXor[np]) << 4));
            }
            const uint32_t* a0 = aF[ks & 1][0];
            const uint32_t* a1 = aF[ks & 1][1];
            const uint32_t* bb = bbF[g & 1];
            mma16816(cc[0][p * 2],     a0, bb[0], bb[1]);
            mma16816(cc[0][p * 2 + 1], a0, bb[2], bb[3]);
            mma16816(cc[1][p * 2],     a1, bb[0], bb[1]);
            mma16816(cc[1][p * 2 + 1], a1, bb[2], bb[3]);
        }
    }

#pragma unroll
    for (int mt = 0; mt < 2; mt++) {
#pragma unroll
        for (int nt = 0; nt < 8; nt++) {
            int colp = n0 + wn0 + nt * 8 + 2 * (lane & 3);
#pragma unroll
            for (int half = 0; half < 2; half++) {
                int rl = wm0 + mt * 16 + (lane >> 2) + half * 8;
                if (m0 + rl < cnt) {
                    int tok = sTok[rl];
                    float* p = out + (size_t)tok * DDIM + colp;
                    red_add_f32(p,     cc[mt][nt][half * 2]);
                    red_add_f32(p + 1, cc[mt][nt][half * 2 + 1]);
                }
            }
        }
    }
}

// ---------------- launch: forked preamble + expert-group ffn1/ffn2 pipelining ----
extern "C" void kernel_launch(void* const* d_in, const int* in_sizes, int n_in,
                              void* d_out, int out_size) {
    const float* x  = (const float*)d_in[0];
    const float* gw = (const float*)d_in[1];
    const float* wg = (const float*)d_in[2];
    const float* wu = (const float*)d_in[3];
    const float* wd = (const float*)d_in[4];

    static cudaStream_t s1 = nullptr, s2 = nullptr;
    static cudaEvent_t evRoot = nullptr, ev1 = nullptr, evA = nullptr, evJ = nullptr;
    if (s1 == nullptr) {
        cudaStreamCreateWithFlags(&s1, cudaStreamNonBlocking);
        cudaStreamCreateWithFlags(&s2, cudaStreamNonBlocking);
        cudaEventCreateWithFlags(&evRoot, cudaEventDisableTiming);
        cudaEventCreateWithFlags(&ev1, cudaEventDisableTiming);
        cudaEventCreateWithFlags(&evA, cudaEventDisableTiming);
        cudaEventCreateWithFlags(&evJ, cudaEventDisableTiming);
        cudaFuncSetAttribute(k_ffn1, cudaFuncAttributeMaxDynamicSharedMemorySize, F1_SMEM);
        cudaFuncSetAttribute(k_ffn2, cudaFuncAttributeMaxDynamicSharedMemorySize, F2_SMEM);
    }

    const int n4w = (int)((size_t)ENUM * IDIM * DDIM / 4);
    __half* wgh; cudaGetSymbolAddress((void**)&wgh, g_wgh);
    __half* wuh; cudaGetSymbolAddress((void**)&wuh, g_wuh);
    __half* wdh; cudaGetSymbolAddress((void**)&wdh, g_wdh);

    // fork point
    cudaEventRecord(evRoot, 0);

    // branch s1: convert gate/up weights (gates ffn1_A)
    cudaStreamWaitEvent(s1, evRoot, 0);
    dim3 gC2((n4w + 511) / 512, 2);
    k_cvt_gu<<<gC2, 256, 0, s1>>>((const float4*)wg, (const float4*)wu,
                                  (__half2*)wgh, (__half2*)wuh, n4w);
    cudaEventRecord(ev1, s1);

    // branch s2: convert down weights + zero d_out (gates ffn2_A in-order on s2)
    cudaStreamWaitEvent(s2, evRoot, 0);
    k_cvt_one<<<(n4w + 511) / 512, 256, 0, s2>>>((const float4*)wd, (__half2*)wdh, n4w);
    k_zero_dout<<<(TTOK * DDIM / 4) / 256, 256, 0, s2>>>((float4*)d_out);

    // main stream: counter zero + router (critical path for ffn1)
    k_zero_cnt<<<1, 32>>>();
    k_router<<<TTOK / 8, 256>>>(x, gw);

    // ffn1 group A (experts 0-3)
    cudaStreamWaitEvent(0, ev1, 0);
    dim3 gA(IDIM / 64, TTOK / 128, ENUM / 2);   // (22, 32, 4)
    k_ffn1<<<gA, 256, F1_SMEM>>>(0);
    cudaEventRecord(evA, 0);

    // ffn1 group B (experts 4-7) on main, overlapped with ffn2_A on s2
    k_ffn1<<<gA, 256, F1_SMEM>>>(ENUM / 2);

    // ffn2 group A on s2 (after its cvt_wd + zero_dout, and after ffn1_A)
    cudaStreamWaitEvent(s2, evA, 0);
    dim3 gB(DDIM / 128, TTOK / 128, ENUM / 2);  // (8, 32, 4)
    k_ffn2<<<gB, 256, F2_SMEM, s2>>>((float*)d_out, 0);
    cudaEventRecord(evJ, s2);

    // ffn2 group B on main (after ffn1_B in-order; d_out zero + wd cvt joined via evJ path)
    cudaStreamWaitEvent(0, evJ, 0);
    k_ffn2<<<gB, 256, F2_SMEM>>>((float*)d_out, ENUM / 2);
}

// round 10
// speedup vs baseline: 1.0462x; 1.0462x over previous
#include <cuda_runtime.h>
#include <cuda_fp16.h>
#include <cstdint>

// Problem constants (B=2, S=2048, D=1024, E=8, I=1408, TOPK=2)
#define TTOK 4096
#define DDIM 1024
#define ENUM 8
#define IDIM 1408

#define BKH 64        // K per tile in halves = 128 bytes/row
#define KSTEPS 4      // k16 steps per tile

// ---------------- static device scratch (no allocations allowed) ----------------
__device__ int    g_cnt[ENUM];
__device__ int    g_tok[ENUM * TTOK];
__device__ int    g_slot[ENUM * TTOK];
__device__ float  g_prob[ENUM * TTOK];
__device__ __half g_xh[(size_t)TTOK * DDIM];
__device__ __half g_wgh[(size_t)ENUM * IDIM * DDIM];
__device__ __half g_wuh[(size_t)ENUM * IDIM * DDIM];
__device__ __half g_wdh[(size_t)ENUM * DDIM * IDIM];
__device__ __half g_h[(size_t)ENUM * TTOK * IDIM];

// ---------------- helpers ----------------
__device__ __forceinline__ uint32_t smem_u32(const void* p) {
    return (uint32_t)__cvta_generic_to_shared(p);
}

__device__ __forceinline__ void mma16816(float* c, const uint32_t* a, uint32_t b0, uint32_t b1) {
    asm volatile(
        "mma.sync.aligned.m16n8k16.row.col.f32.f16.f16.f32 "
        "{%0,%1,%2,%3},{%4,%5,%6,%7},{%8,%9},{%0,%1,%2,%3};\n"
        : "+f"(c[0]), "+f"(c[1]), "+f"(c[2]), "+f"(c[3])
        : "r"(a[0]), "r"(a[1]), "r"(a[2]), "r"(a[3]), "r"(b0), "r"(b1));
}

__device__ __forceinline__ void ldsm_x4(uint32_t* r, uint32_t addr) {
    asm volatile("ldmatrix.sync.aligned.m8n8.x4.shared.b16 {%0,%1,%2,%3}, [%4];"
                 : "=r"(r[0]), "=r"(r[1]), "=r"(r[2]), "=r"(r[3]) : "r"(addr));
}

__device__ __forceinline__ void cpa16(uint32_t saddr, const void* g) {
    asm volatile("cp.async.cg.shared.global [%0], [%1], 16;\n" :: "r"(saddr), "l"(g));
}
__device__ __forceinline__ void cpa_commit() { asm volatile("cp.async.commit_group;\n"); }
template <int N>
__device__ __forceinline__ void cpa_wait() { asm volatile("cp.async.wait_group %0;\n" :: "n"(N)); }

__device__ __forceinline__ void red_add_f32(float* p, float v) {
    asm volatile("red.global.add.f32 [%0], %1;" :: "l"(p), "f"(v) : "memory");
}

// ---------------- kernel: zero d_out (on s2, hidden under ffn1) ----------------
__global__ void k_zero_dout(float4* __restrict__ out) {
    int i = blockIdx.x * blockDim.x + threadIdx.x;
    out[i] = make_float4(0.f, 0.f, 0.f, 0.f);
}

// ---------------- kernels: fp32 -> fp16 convert (streaming reads, 4 f4/thread) ----
__global__ void k_cvt_gu(const float4* __restrict__ s0, const float4* __restrict__ s1,
                         __half2* __restrict__ d0, __half2* __restrict__ d1, int n4) {
    const float4* src = (blockIdx.y == 0) ? s0 : s1;
    __half2* dst = (blockIdx.y == 0) ? d0 : d1;
    int base = blockIdx.x * (blockDim.x * 4) + threadIdx.x;
#pragma unroll
    for (int k = 0; k < 4; k++) {
        int i = base + k * 256;
        if (i < n4) {
            float4 v = __ldcs(src + i);
            dst[i * 2]     = __floats2half2_rn(v.x, v.y);
            dst[i * 2 + 1] = __floats2half2_rn(v.z, v.w);
        }
    }
}

__global__ void k_cvt_one(const float4* __restrict__ src, __half2* __restrict__ dst, int n4) {
    int base = blockIdx.x * (blockDim.x * 4) + threadIdx.x;
#pragma unroll
    for (int k = 0; k < 4; k++) {
        int i = base + k * 256;
        if (i < n4) {
            float4 v = __ldcs(src + i);
            dst[i * 2]     = __floats2half2_rn(v.x, v.y);
            dst[i * 2 + 1] = __floats2half2_rn(v.z, v.w);
        }
    }
}

// ---------------- kernel 1: router (gate_w staged in smem) ----------------
__global__ __launch_bounds__(256) void k_router(const float* __restrict__ x,
                                                const float* __restrict__ gw) {
    __shared__ float4 sGw[ENUM * DDIM / 4];   // 32 KB

    const int tid = threadIdx.x;
#pragma unroll
    for (int i = 0; i < ENUM * DDIM / 4 / 256; i++)
        sGw[tid + i * 256] = ((const float4*)gw)[tid + i * 256];
    __syncthreads();

    const int wid = tid >> 5;
    const int lane = tid & 31;
    const int tok = blockIdx.x * 8 + wid;

    const float4* xr = (const float4*)(x + (size_t)tok * DDIM);
    __half2* xh2 = (__half2*)(g_xh + (size_t)tok * DDIM);

    float acc[ENUM];
#pragma unroll
    for (int e = 0; e < ENUM; e++) acc[e] = 0.f;

#pragma unroll
    for (int it = 0; it < DDIM / 4 / 32; it++) {
        int c = lane + it * 32;
        float4 xv = xr[c];
        xh2[c * 2]     = __floats2half2_rn(xv.x, xv.y);
        xh2[c * 2 + 1] = __floats2half2_rn(xv.z, xv.w);
#pragma unroll
        for (int e = 0; e < ENUM; e++) {
            float4 wv = sGw[e * (DDIM / 4) + c];
            acc[e] += xv.x * wv.x + xv.y * wv.y + xv.z * wv.z + xv.w * wv.w;
        }
    }
#pragma unroll
    for (int e = 0; e < ENUM; e++) {
#pragma unroll
        for (int off = 16; off > 0; off >>= 1)
            acc[e] += __shfl_xor_sync(0xFFFFFFFFu, acc[e], off);
    }

    if (lane == 0) {
        int i0 = 0;
        float s0 = acc[0];
#pragma unroll
        for (int e = 1; e < ENUM; e++)
            if (acc[e] > s0) { s0 = acc[e]; i0 = e; }
        int i1 = -1;
        float s1 = -3.4e38f;
#pragma unroll
        for (int e = 0; e < ENUM; e++)
            if (e != i0 && acc[e] > s1) { s1 = acc[e]; i1 = e; }

        float e1 = expf(s1 - s0);
        float inv = 1.f / (1.f + e1);

        int pos0 = atomicAdd(&g_cnt[i0], 1);
        g_tok[i0 * TTOK + pos0]  = tok;
        g_slot[i0 * TTOK + pos0] = 0;
        g_prob[i0 * TTOK + pos0] = inv;

        int pos1 = atomicAdd(&g_cnt[i1], 1);
        g_tok[i1 * TTOK + pos1]  = tok;
        g_slot[i1 * TTOK + pos1] = 1;
        g_prob[i1 * TTOK + pos1] = e1 * inv;
    }
}

// =====================================================================
// kernel 2: ffn1 — fp16 mma: [128 gathered tokens] x [64 I-cols], G & U,
//           fused silu(g)*u*prob -> g_h (fp16). 3-stage cp.async pipeline
//           + register-fragment software pipelining.  (frozen since R7)
// =====================================================================
#define F1_GOFF 16384
#define F1_UOFF 24576
#define F1_STG  32768
#define F1_KT   (DDIM / BKH)   // 16
#define F1_SMEM (3 * F1_STG + 256)

__global__ __launch_bounds__(256, 2) void k_ffn1() {
    __shared__ int   sTok[128];
    __shared__ float sProb[128];
    extern __shared__ char dynsm[];

    uint32_t raw = smem_u32(dynsm);
    uint32_t sbase = (raw + 127) & ~127u;

    const int e = blockIdx.z;
    const int cnt = g_cnt[e];
    const int m0 = blockIdx.y * 128;
    if (m0 >= cnt) return;
    const int n0 = blockIdx.x * 64;
    const int tid = threadIdx.x;

    if (tid < 128) {
        int rc = min(m0 + tid, cnt - 1);
        sTok[tid]  = g_tok[e * TTOK + rc];
        sProb[tid] = g_prob[e * TTOK + rc];
    }
    __syncthreads();

    const int lane = tid & 31;
    const int wid = tid >> 5;
    const int wm0 = (wid & 3) * 32;
    const int wn0 = (wid >> 2) * 32;
    const int sub = lane >> 3;
    const int l8 = lane & 7;

    const __half* wgb = g_wgh + (size_t)e * IDIM * DDIM;
    const __half* wub = g_wuh + (size_t)e * IDIM * DDIM;

    const __half* aSrc[4];
    uint32_t aDst[4];
#pragma unroll
    for (int i = 0; i < 4; i++) {
        int f = tid + i * 256;
        int row = f >> 3, c = f & 7;
        aDst[i] = row * 128 + ((c ^ (row & 7)) << 4);
        aSrc[i] = g_xh + (size_t)sTok[row] * DDIM + c * 8;
    }
    const __half* gSrc[2];
    const __half* uSrc[2];
    uint32_t wDst[2];
#pragma unroll
    for (int i = 0; i < 2; i++) {
        int f = tid + i * 256;
        int row = f >> 3, c = f & 7;
        wDst[i] = row * 128 + ((c ^ (row & 7)) << 4);
        gSrc[i] = wgb + (size_t)(n0 + row) * DDIM + c * 8;
        uSrc[i] = wub + (size_t)(n0 + row) * DDIM + c * 8;
    }

    auto load_stage = [&](int st, int kt) {
        uint32_t b = sbase + st * F1_STG;
        int kb = kt * BKH;
#pragma unroll
        for (int i = 0; i < 4; i++) cpa16(b + aDst[i], aSrc[i] + kb);
#pragma unroll
        for (int i = 0; i < 2; i++) {
            cpa16(b + F1_GOFF + wDst[i], gSrc[i] + kb);
            cpa16(b + F1_UOFF + wDst[i], uSrc[i] + kb);
        }
    };

    uint32_t aRow[2], aXor[2];
#pragma unroll
    for (int mt = 0; mt < 2; mt++) {
        int row = wm0 + mt * 16 + ((sub & 1) << 3) + l8;
        aRow[mt] = row * 128;
        aXor[mt] = row & 7;
    }
    const uint32_t aBit = sub >> 1;
    uint32_t bRow[2], bXor[2];
#pragma unroll
    for (int p = 0; p < 2; p++) {
        int row = wn0 + p * 16 + ((sub >> 1) << 3) + l8;
        bRow[p] = row * 128;
        bXor[p] = row & 7;
    }
    const uint32_t bBit = sub & 1;

    float cg[2][4][4], cu[2][4][4];
#pragma unroll
    for (int a = 0; a < 2; a++)
#pragma unroll
        for (int b = 0; b < 4; b++)
#pragma unroll
            for (int c = 0; c < 4; c++) { cg[a][b][c] = 0.f; cu[a][b][c] = 0.f; }

    load_stage(0, 0);
    cpa_commit();
    load_stage(1, 1);
    cpa_commit();

    for (int kt = 0; kt < F1_KT; kt++) {
        cpa_wait<1>();
        __syncthreads();
        if (kt + 2 < F1_KT) {
            int st = (kt + 2) % 3;
            load_stage(st, kt + 2);
        }
        cpa_commit();

        uint32_t stA = sbase + (kt % 3) * F1_STG;
        uint32_t stG = stA + F1_GOFF;
        uint32_t stU = stA + F1_UOFF;

        uint32_t aF[2][2][4];
        uint32_t bgF[2][4], buF[2][4];
        ldsm_x4(aF[0][0], stA + aRow[0] + ((aBit ^ aXor[0]) << 4));
        ldsm_x4(aF[0][1], stA + aRow[1] + ((aBit ^ aXor[1]) << 4));
        ldsm_x4(bgF[0], stG + bRow[0] + ((bBit ^ bXor[0]) << 4));
        ldsm_x4(buF[0], stU + bRow[0] + ((bBit ^ bXor[0]) << 4));
#pragma unroll
        for (int g = 0; g < 2 * KSTEPS; g++) {
            const int ks = g >> 1, p = g & 1;
            const int gn = g + 1;
            if (gn < 2 * KSTEPS) {
                const int nks = gn >> 1, np = gn & 1;
                if (np == 0) {
                    uint32_t ca = (uint32_t)(nks * 2) + aBit;
                    ldsm_x4(aF[nks & 1][0], stA + aRow[0] + ((ca ^ aXor[0]) << 4));
                    ldsm_x4(aF[nks & 1][1], stA + aRow[1] + ((ca ^ aXor[1]) << 4));
                }
                uint32_t cb = (uint32_t)(nks * 2) + bBit;
                ldsm_x4(bgF[gn & 1], stG + bRow[np] + ((cb ^ bXor[np]) << 4));
                ldsm_x4(buF[gn & 1], stU + bRow[np] + ((cb ^ bXor[np]) << 4));
            }
            const uint32_t* a0 = aF[ks & 1][0];
            const uint32_t* a1 = aF[ks & 1][1];
            const uint32_t* bg = bgF[g & 1];
            const uint32_t* bu = buF[g & 1];
            mma16816(cg[0][p * 2],     a0, bg[0], bg[1]);
            mma16816(cg[0][p * 2 + 1], a0, bg[2], bg[3]);
            mma16816(cu[0][p * 2],     a0, bu[0], bu[1]);
            mma16816(cu[0][p * 2 + 1], a0, bu[2], bu[3]);
            mma16816(cg[1][p * 2],     a1, bg[0], bg[1]);
            mma16816(cg[1][p * 2 + 1], a1, bg[2], bg[3]);
            mma16816(cu[1][p * 2],     a1, bu[0], bu[1]);
            mma16816(cu[1][p * 2 + 1], a1, bu[2], bu[3]);
        }
    }

    __half* hb = g_h + (size_t)e * TTOK * IDIM;
#pragma unroll
    for (int mt = 0; mt < 2; mt++) {
#pragma unroll
        for (int nt = 0; nt < 4; nt++) {
            int colp = n0 + wn0 + nt * 8 + 2 * (lane & 3);
#pragma unroll
            for (int half = 0; half < 2; half++) {
                int rl = wm0 + mt * 16 + (lane >> 2) + half * 8;
                if (m0 + rl < cnt) {
                    float g0 = cg[mt][nt][half * 2], g1 = cg[mt][nt][half * 2 + 1];
                    float u0 = cu[mt][nt][half * 2], u1 = cu[mt][nt][half * 2 + 1];
                    float p = sProb[rl];
                    float h0 = (g0 / (1.f + __expf(-g0))) * u0 * p;
                    float h1 = (g1 / (1.f + __expf(-g1))) * u1 * p;
                    *(__half2*)(hb + (size_t)(m0 + rl) * IDIM + colp) = __floats2half2_rn(h0, h1);
                }
            }
        }
    }
}

// =====================================================================
// kernel 3: ffn2 — fp16 mma: [128 slot rows] x [128 D-cols], K=1408
//           3-stage cp.async pipeline + register-fragment pipelining;
//           red.add directly into d_out.  (frozen since R7)
// =====================================================================
#define F2_BOFF 16384
#define F2_STG  32768
#define F2_KT   (IDIM / BKH)   // 22
#define F2_SMEM (3 * F2_STG + 256)

__global__ __launch_bounds__(256, 2) void k_ffn2(float* __restrict__ out) {
    __shared__ int sTok[128];
    extern __shared__ char dynsm[];

    uint32_t raw = smem_u32(dynsm);
    uint32_t sbase = (raw + 127) & ~127u;

    const int e = blockIdx.z;
    const int cnt = g_cnt[e];
    const int m0 = blockIdx.y * 128;
    if (m0 >= cnt) return;
    const int n0 = blockIdx.x * 128;
    const int tid = threadIdx.x;

    if (tid < 128) {
        int rc = min(m0 + tid, cnt - 1);
        sTok[tid] = g_tok[e * TTOK + rc];
    }
    __syncthreads();

    const int lane = tid & 31;
    const int wid = tid >> 5;
    const int wm0 = (wid & 3) * 32;
    const int wn0 = (wid >> 2) * 64;
    const int sub = lane >> 3;
    const int l8 = lane & 7;

    const __half* hb  = g_h + (size_t)e * TTOK * IDIM;
    const __half* wdb = g_wdh + (size_t)e * DDIM * IDIM;

    const __half* aSrc[4];
    const __half* bSrc[4];
    uint32_t tDst[4];
#pragma unroll
    for (int i = 0; i < 4; i++) {
        int f = tid + i * 256;
        int row = f >> 3, c = f & 7;
        tDst[i] = row * 128 + ((c ^ (row & 7)) << 4);
        int rc = min(m0 + row, cnt - 1);
        aSrc[i] = hb + (size_t)rc * IDIM + c * 8;
        bSrc[i] = wdb + (size_t)(n0 + row) * IDIM + c * 8;
    }

    auto load_stage = [&](int st, int kt) {
        uint32_t b = sbase + st * F2_STG;
        int kb = kt * BKH;
#pragma unroll
        for (int i = 0; i < 4; i++) {
            cpa16(b + tDst[i], aSrc[i] + kb);
            cpa16(b + F2_BOFF + tDst[i], bSrc[i] + kb);
        }
    };

    uint32_t aRow[2], aXor[2];
#pragma unroll
    for (int mt = 0; mt < 2; mt++) {
        int row = wm0 + mt * 16 + ((sub & 1) << 3) + l8;
        aRow[mt] = row * 128;
        aXor[mt] = row & 7;
    }
    const uint32_t aBit = sub >> 1;
    uint32_t bRow[4], bXor[4];
#pragma unroll
    for (int p = 0; p < 4; p++) {
        int row = wn0 + p * 16 + ((sub >> 1) << 3) + l8;
        bRow[p] = row * 128;
        bXor[p] = row & 7;
    }
    const uint32_t bBit = sub & 1;

    float cc[2][8][4];
#pragma unroll
    for (int a = 0; a < 2; a++)
#pragma unroll
        for (int b = 0; b < 8; b++)
#pragma unroll
            for (int c = 0; c < 4; c++) cc[a][b][c] = 0.f;

    load_stage(0, 0);
    cpa_commit();
    load_stage(1, 1);
    cpa_commit();

    for (int kt = 0; kt < F2_KT; kt++) {
        cpa_wait<1>();
        __syncthreads();
        if (kt + 2 < F2_KT) {
            int st = (kt + 2) % 3;
            load_stage(st, kt + 2);
        }
        cpa_commit();

        uint32_t stA = sbase + (kt % 3) * F2_STG;
        uint32_t stB = stA + F2_BOFF;

        uint32_t aF[2][2][4];
        uint32_t bbF[2][4];
        ldsm_x4(aF[0][0], stA + aRow[0] + ((aBit ^ aXor[0]) << 4));
        ldsm_x4(aF[0][1], stA + aRow[1] + ((aBit ^ aXor[1]) << 4));
        ldsm_x4(bbF[0], stB + bRow[0] + ((bBit ^ bXor[0]) << 4));
#pragma unroll
        for (int g = 0; g < 4 * KSTEPS; g++) {
            const int ks = g >> 2, p = g & 3;
            const int gn = g + 1;
            if (gn < 4 * KSTEPS) {
                const int nks = gn >> 2, np = gn & 3;
                if (np == 0) {
                    uint32_t ca = (uint32_t)(nks * 2) + aBit;
                    ldsm_x4(aF[nks & 1][0], stA + aRow[0] + ((ca ^ aXor[0]) << 4));
                    ldsm_x4(aF[nks & 1][1], stA + aRow[1] + ((ca ^ aXor[1]) << 4));
                }
                uint32_t cb = (uint32_t)(nks * 2) + bBit;
                ldsm_x4(bbF[gn & 1], stB + bRow[np] + ((cb ^ bXor[np]) << 4));
            }
            const uint32_t* a0 = aF[ks & 1][0];
            const uint32_t* a1 = aF[ks & 1][1];
            const uint32_t* bb = bbF[g & 1];
            mma16816(cc[0][p * 2],     a0, bb[0], bb[1]);
            mma16816(cc[0][p * 2 + 1], a0, bb[2], bb[3]);
            mma16816(cc[1][p * 2],     a1, bb[0], bb[1]);
            mma16816(cc[1][p * 2 + 1], a1, bb[2], bb[3]);
        }
    }

#pragma unroll
    for (int mt = 0; mt < 2; mt++) {
#pragma unroll
        for (int nt = 0; nt < 8; nt++) {
            int colp = n0 + wn0 + nt * 8 + 2 * (lane & 3);
#pragma unroll
            for (int half = 0; half < 2; half++) {
                int rl = wm0 + mt * 16 + (lane >> 2) + half * 8;
                if (m0 + rl < cnt) {
                    int tok = sTok[rl];
                    float* p = out + (size_t)tok * DDIM + colp;
                    red_add_f32(p,     cc[mt][nt][half * 2]);
                    red_add_f32(p + 1, cc[mt][nt][half * 2 + 1]);
                }
            }
        }
    }
}

// ---------------- launch: R8 schedule, s2 deferred behind cvt_gu ----------------
extern "C" void kernel_launch(void* const* d_in, const int* in_sizes, int n_in,
                              void* d_out, int out_size) {
    const float* x  = (const float*)d_in[0];
    const float* gw = (const float*)d_in[1];
    const float* wg = (const float*)d_in[2];
    const float* wu = (const float*)d_in[3];
    const float* wd = (const float*)d_in[4];

    static cudaStream_t s1 = nullptr, s2 = nullptr;
    static cudaEvent_t evRoot = nullptr, ev1 = nullptr, ev2 = nullptr;
    if (s1 == nullptr) {
        cudaStreamCreateWithFlags(&s1, cudaStreamNonBlocking);
        cudaStreamCreateWithFlags(&s2, cudaStreamNonBlocking);
        cudaEventCreateWithFlags(&evRoot, cudaEventDisableTiming);
        cudaEventCreateWithFlags(&ev1, cudaEventDisableTiming);
        cudaEventCreateWithFlags(&ev2, cudaEventDisableTiming);
        cudaFuncSetAttribute(k_ffn1, cudaFuncAttributeMaxDynamicSharedMemorySize, F1_SMEM);
        cudaFuncSetAttribute(k_ffn2, cudaFuncAttributeMaxDynamicSharedMemorySize, F2_SMEM);
    }

    const int n4w = (int)((size_t)ENUM * IDIM * DDIM / 4);
    __half* wgh; cudaGetSymbolAddress((void**)&wgh, g_wgh);
    __half* wuh; cudaGetSymbolAddress((void**)&wuh, g_wuh);
    __half* wdh; cudaGetSymbolAddress((void**)&wdh, g_wdh);
    int* cntp;   cudaGetSymbolAddress((void**)&cntp, g_cnt);

    // fork point
    cudaEventRecord(evRoot, 0);

    // branch s1: convert gate/up weights (gates ffn1) — sole large consumer of
    // DRAM bandwidth during the preamble window
    cudaStreamWaitEvent(s1, evRoot, 0);
    dim3 gC2((n4w + 1023) / 1024, 2);
    k_cvt_gu<<<gC2, 256, 0, s1>>>((const float4*)wg, (const float4*)wu,
                                  (__half2*)wgh, (__half2*)wuh, n4w);
    cudaEventRecord(ev1, s1);

    // branch s2: DEFERRED until cvt_gu completes so its 86MB of traffic runs
    // under ffn1 (DRAM idle there), not against the critical path.
    cudaStreamWaitEvent(s2, ev1, 0);
    k_cvt_one<<<(n4w + 1023) / 1024, 256, 0, s2>>>((const float4*)wd, (__half2*)wdh, n4w);
    k_zero_dout<<<(TTOK * DDIM / 4) / 256, 256, 0, s2>>>((float4*)d_out);
    cudaEventRecord(ev2, s2);

    // main stream: counter zero (graph memset node) + router
    cudaMemsetAsync(cntp, 0, ENUM * sizeof(int), 0);
    k_router<<<TTOK / 8, 256>>>(x, gw);

    cudaStreamWaitEvent(0, ev1, 0);
    dim3 gA(IDIM / 64, TTOK / 128, ENUM);   // (22, 32, 8)
    k_ffn1<<<gA, 256, F1_SMEM>>>();

    cudaStreamWaitEvent(0, ev2, 0);
    dim3 gB(DDIM / 128, TTOK / 128, ENUM);  // (8, 32, 8)
    k_ffn2<<<gB, 256, F2_SMEM>>>((float*)d_out);
}

// round 11
// speedup vs baseline: 1.0491x; 1.0028x over previous
#include <cuda_runtime.h>
#include <cuda_fp16.h>
#include <cstdint>

// Problem constants (B=2, S=2048, D=1024, E=8, I=1408, TOPK=2)
#define TTOK 4096
#define DDIM 1024
#define ENUM 8
#define IDIM 1408

#define BKH 64        // K per tile in halves = 128 bytes/row
#define KSTEPS 4      // k16 steps per tile

// ---------------- static device scratch (no allocations allowed) ----------------
__device__ int    g_cnt[ENUM];
__device__ int    g_tok[ENUM * TTOK];
__device__ int    g_slot[ENUM * TTOK];
__device__ float  g_prob[ENUM * TTOK];
__device__ __half g_xh[(size_t)TTOK * DDIM];
__device__ __half g_wgh[(size_t)ENUM * IDIM * DDIM];
__device__ __half g_wuh[(size_t)ENUM * IDIM * DDIM];
__device__ __half g_wdh[(size_t)ENUM * DDIM * IDIM];
__device__ __half g_h[(size_t)ENUM * TTOK * IDIM];

// ---------------- helpers ----------------
__device__ __forceinline__ uint32_t smem_u32(const void* p) {
    return (uint32_t)__cvta_generic_to_shared(p);
}

__device__ __forceinline__ void mma16816(float* c, const uint32_t* a, uint32_t b0, uint32_t b1) {
    asm volatile(
        "mma.sync.aligned.m16n8k16.row.col.f32.f16.f16.f32 "
        "{%0,%1,%2,%3},{%4,%5,%6,%7},{%8,%9},{%0,%1,%2,%3};\n"
        : "+f"(c[0]), "+f"(c[1]), "+f"(c[2]), "+f"(c[3])
        : "r"(a[0]), "r"(a[1]), "r"(a[2]), "r"(a[3]), "r"(b0), "r"(b1));
}

__device__ __forceinline__ void ldsm_x4(uint32_t* r, uint32_t addr) {
    asm volatile("ldmatrix.sync.aligned.m8n8.x4.shared.b16 {%0,%1,%2,%3}, [%4];"
                 : "=r"(r[0]), "=r"(r[1]), "=r"(r[2]), "=r"(r[3]) : "r"(addr));
}

__device__ __forceinline__ void cpa16(uint32_t saddr, const void* g) {
    asm volatile("cp.async.cg.shared.global [%0], [%1], 16;\n" :: "r"(saddr), "l"(g));
}
__device__ __forceinline__ void cpa_commit() { asm volatile("cp.async.commit_group;\n"); }
template <int N>
__device__ __forceinline__ void cpa_wait() { asm volatile("cp.async.wait_group %0;\n" :: "n"(N)); }

__device__ __forceinline__ void red_add_f32(float* p, float v) {
    asm volatile("red.global.add.f32 [%0], %1;" :: "l"(p), "f"(v) : "memory");
}

// ---------------- kernel: zero d_out (on s2, hidden under ffn1) ----------------
__global__ void k_zero_dout(float4* __restrict__ out) {
    int i = blockIdx.x * blockDim.x + threadIdx.x;
    out[i] = make_float4(0.f, 0.f, 0.f, 0.f);
}

// ---------------- kernels: fp32 -> fp16 convert (streaming reads, 4 f4/thread) ----
// Converts an expert-half of BOTH wg and wu (blockIdx.y selects tensor).
__global__ void k_cvt_gu(const float4* __restrict__ s0, const float4* __restrict__ s1,
                         __half2* __restrict__ d0, __half2* __restrict__ d1, int n4) {
    const float4* src = (blockIdx.y == 0) ? s0 : s1;
    __half2* dst = (blockIdx.y == 0) ? d0 : d1;
    int base = blockIdx.x * (blockDim.x * 4) + threadIdx.x;
#pragma unroll
    for (int k = 0; k < 4; k++) {
        int i = base + k * 256;
        if (i < n4) {
            float4 v = __ldcs(src + i);
            dst[i * 2]     = __floats2half2_rn(v.x, v.y);
            dst[i * 2 + 1] = __floats2half2_rn(v.z, v.w);
        }
    }
}

__global__ void k_cvt_one(const float4* __restrict__ src, __half2* __restrict__ dst, int n4) {
    int base = blockIdx.x * (blockDim.x * 4) + threadIdx.x;
#pragma unroll
    for (int k = 0; k < 4; k++) {
        int i = base + k * 256;
        if (i < n4) {
            float4 v = __ldcs(src + i);
            dst[i * 2]     = __floats2half2_rn(v.x, v.y);
            dst[i * 2 + 1] = __floats2half2_rn(v.z, v.w);
        }
    }
}

// ---------------- kernel 1: router (gate_w staged in smem) ----------------
__global__ __launch_bounds__(256) void k_router(const float* __restrict__ x,
                                                const float* __restrict__ gw) {
    __shared__ float4 sGw[ENUM * DDIM / 4];   // 32 KB

    const int tid = threadIdx.x;
#pragma unroll
    for (int i = 0; i < ENUM * DDIM / 4 / 256; i++)
        sGw[tid + i * 256] = ((const float4*)gw)[tid + i * 256];
    __syncthreads();

    const int wid = tid >> 5;
    const int lane = tid & 31;
    const int tok = blockIdx.x * 8 + wid;

    const float4* xr = (const float4*)(x + (size_t)tok * DDIM);
    __half2* xh2 = (__half2*)(g_xh + (size_t)tok * DDIM);

    float acc[ENUM];
#pragma unroll
    for (int e = 0; e < ENUM; e++) acc[e] = 0.f;

#pragma unroll
    for (int it = 0; it < DDIM / 4 / 32; it++) {
        int c = lane + it * 32;
        float4 xv = xr[c];
        xh2[c * 2]     = __floats2half2_rn(xv.x, xv.y);
        xh2[c * 2 + 1] = __floats2half2_rn(xv.z, xv.w);
#pragma unroll
        for (int e = 0; e < ENUM; e++) {
            float4 wv = sGw[e * (DDIM / 4) + c];
            acc[e] += xv.x * wv.x + xv.y * wv.y + xv.z * wv.z + xv.w * wv.w;
        }
    }
#pragma unroll
    for (int e = 0; e < ENUM; e++) {
#pragma unroll
        for (int off = 16; off > 0; off >>= 1)
            acc[e] += __shfl_xor_sync(0xFFFFFFFFu, acc[e], off);
    }

    if (lane == 0) {
        int i0 = 0;
        float s0 = acc[0];
#pragma unroll
        for (int e = 1; e < ENUM; e++)
            if (acc[e] > s0) { s0 = acc[e]; i0 = e; }
        int i1 = -1;
        float s1 = -3.4e38f;
#pragma unroll
        for (int e = 0; e < ENUM; e++)
            if (e != i0 && acc[e] > s1) { s1 = acc[e]; i1 = e; }

        float e1 = expf(s1 - s0);
        float inv = 1.f / (1.f + e1);

        int pos0 = atomicAdd(&g_cnt[i0], 1);
        g_tok[i0 * TTOK + pos0]  = tok;
        g_slot[i0 * TTOK + pos0] = 0;
        g_prob[i0 * TTOK + pos0] = inv;

        int pos1 = atomicAdd(&g_cnt[i1], 1);
        g_tok[i1 * TTOK + pos1]  = tok;
        g_slot[i1 * TTOK + pos1] = 1;
        g_prob[i1 * TTOK + pos1] = e1 * inv;
    }
}

// =====================================================================
// kernel 2: ffn1 — fp16 mma: [128 gathered tokens] x [64 I-cols], G & U,
//           fused silu(g)*u*prob -> g_h (fp16). 3-stage cp.async pipeline
//           + register-fragment software pipelining. ebase = expert group.
// =====================================================================
#define F1_GOFF 16384
#define F1_UOFF 24576
#define F1_STG  32768
#define F1_KT   (DDIM / BKH)   // 16
#define F1_SMEM (3 * F1_STG + 256)

__global__ __launch_bounds__(256, 2) void k_ffn1(int ebase) {
    __shared__ int   sTok[128];
    __shared__ float sProb[128];
    extern __shared__ char dynsm[];

    uint32_t raw = smem_u32(dynsm);
    uint32_t sbase = (raw + 127) & ~127u;

    const int e = ebase + blockIdx.z;
    const int cnt = g_cnt[e];
    const int m0 = blockIdx.y * 128;
    if (m0 >= cnt) return;
    const int n0 = blockIdx.x * 64;
    const int tid = threadIdx.x;

    if (tid < 128) {
        int rc = min(m0 + tid, cnt - 1);
        sTok[tid]  = g_tok[e * TTOK + rc];
        sProb[tid] = g_prob[e * TTOK + rc];
    }
    __syncthreads();

    const int lane = tid & 31;
    const int wid = tid >> 5;
    const int wm0 = (wid & 3) * 32;
    const int wn0 = (wid >> 2) * 32;
    const int sub = lane >> 3;
    const int l8 = lane & 7;

    const __half* wgb = g_wgh + (size_t)e * IDIM * DDIM;
    const __half* wub = g_wuh + (size_t)e * IDIM * DDIM;

    const __half* aSrc[4];
    uint32_t aDst[4];
#pragma unroll
    for (int i = 0; i < 4; i++) {
        int f = tid + i * 256;
        int row = f >> 3, c = f & 7;
        aDst[i] = row * 128 + ((c ^ (row & 7)) << 4);
        aSrc[i] = g_xh + (size_t)sTok[row] * DDIM + c * 8;
    }
    const __half* gSrc[2];
    const __half* uSrc[2];
    uint32_t wDst[2];
#pragma unroll
    for (int i = 0; i < 2; i++) {
        int f = tid + i * 256;
        int row = f >> 3, c = f & 7;
        wDst[i] = row * 128 + ((c ^ (row & 7)) << 4);
        gSrc[i] = wgb + (size_t)(n0 + row) * DDIM + c * 8;
        uSrc[i] = wub + (size_t)(n0 + row) * DDIM + c * 8;
    }

    auto load_stage = [&](int st, int kt) {
        uint32_t b = sbase + st * F1_STG;
        int kb = kt * BKH;
#pragma unroll
        for (int i = 0; i < 4; i++) cpa16(b + aDst[i], aSrc[i] + kb);
#pragma unroll
        for (int i = 0; i < 2; i++) {
            cpa16(b + F1_GOFF + wDst[i], gSrc[i] + kb);
            cpa16(b + F1_UOFF + wDst[i], uSrc[i] + kb);
        }
    };

    uint32_t aRow[2], aXor[2];
#pragma unroll
    for (int mt = 0; mt < 2; mt++) {
        int row = wm0 + mt * 16 + ((sub & 1) << 3) + l8;
        aRow[mt] = row * 128;
        aXor[mt] = row & 7;
    }
    const uint32_t aBit = sub >> 1;
    uint32_t bRow[2], bXor[2];
#pragma unroll
    for (int p = 0; p < 2; p++) {
        int row = wn0 + p * 16 + ((sub >> 1) << 3) + l8;
        bRow[p] = row * 128;
        bXor[p] = row & 7;
    }
    const uint32_t bBit = sub & 1;

    float cg[2][4][4], cu[2][4][4];
#pragma unroll
    for (int a = 0; a < 2; a++)
#pragma unroll
        for (int b = 0; b < 4; b++)
#pragma unroll
            for (int c = 0; c < 4; c++) { cg[a][b][c] = 0.f; cu[a][b][c] = 0.f; }

    load_stage(0, 0);
    cpa_commit();
    load_stage(1, 1);
    cpa_commit();

    for (int kt = 0; kt < F1_KT; kt++) {
        cpa_wait<1>();
        __syncthreads();
        if (kt + 2 < F1_KT) {
            int st = (kt + 2) % 3;
            load_stage(st, kt + 2);
        }
        cpa_commit();

        uint32_t stA = sbase + (kt % 3) * F1_STG;
        uint32_t stG = stA + F1_GOFF;
        uint32_t stU = stA + F1_UOFF;

        uint32_t aF[2][2][4];
        uint32_t bgF[2][4], buF[2][4];
        ldsm_x4(aF[0][0], stA + aRow[0] + ((aBit ^ aXor[0]) << 4));
        ldsm_x4(aF[0][1], stA + aRow[1] + ((aBit ^ aXor[1]) << 4));
        ldsm_x4(bgF[0], stG + bRow[0] + ((bBit ^ bXor[0]) << 4));
        ldsm_x4(buF[0], stU + bRow[0] + ((bBit ^ bXor[0]) << 4));
#pragma unroll
        for (int g = 0; g < 2 * KSTEPS; g++) {
            const int ks = g >> 1, p = g & 1;
            const int gn = g + 1;
            if (gn < 2 * KSTEPS) {
                const int nks = gn >> 1, np = gn & 1;
                if (np == 0) {
                    uint32_t ca = (uint32_t)(nks * 2) + aBit;
                    ldsm_x4(aF[nks & 1][0], stA + aRow[0] + ((ca ^ aXor[0]) << 4));
                    ldsm_x4(aF[nks & 1][1], stA + aRow[1] + ((ca ^ aXor[1]) << 4));
                }
                uint32_t cb = (uint32_t)(nks * 2) + bBit;
                ldsm_x4(bgF[gn & 1], stG + bRow[np] + ((cb ^ bXor[np]) << 4));
                ldsm_x4(buF[gn & 1], stU + bRow[np] + ((cb ^ bXor[np]) << 4));
            }
            const uint32_t* a0 = aF[ks & 1][0];
            const uint32_t* a1 = aF[ks & 1][1];
            const uint32_t* bg = bgF[g & 1];
            const uint32_t* bu = buF[g & 1];
            mma16816(cg[0][p * 2],     a0, bg[0], bg[1]);
            mma16816(cg[0][p * 2 + 1], a0, bg[2], bg[3]);
            mma16816(cu[0][p * 2],     a0, bu[0], bu[1]);
            mma16816(cu[0][p * 2 + 1], a0, bu[2], bu[3]);
            mma16816(cg[1][p * 2],     a1, bg[0], bg[1]);
            mma16816(cg[1][p * 2 + 1], a1, bg[2], bg[3]);
            mma16816(cu[1][p * 2],     a1, bu[0], bu[1]);
            mma16816(cu[1][p * 2 + 1], a1, bu[2], bu[3]);
        }
    }

    __half* hb = g_h + (size_t)e * TTOK * IDIM;
#pragma unroll
    for (int mt = 0; mt < 2; mt++) {
#pragma unroll
        for (int nt = 0; nt < 4; nt++) {
            int colp = n0 + wn0 + nt * 8 + 2 * (lane & 3);
#pragma unroll
            for (int half = 0; half < 2; half++) {
                int rl = wm0 + mt * 16 + (lane >> 2) + half * 8;
                if (m0 + rl < cnt) {
                    float g0 = cg[mt][nt][half * 2], g1 = cg[mt][nt][half * 2 + 1];
                    float u0 = cu[mt][nt][half * 2], u1 = cu[mt][nt][half * 2 + 1];
                    float p = sProb[rl];
                    float h0 = (g0 / (1.f + __expf(-g0))) * u0 * p;
                    float h1 = (g1 / (1.f + __expf(-g1))) * u1 * p;
                    *(__half2*)(hb + (size_t)(m0 + rl) * IDIM + colp) = __floats2half2_rn(h0, h1);
                }
            }
        }
    }
}

// =====================================================================
// kernel 3: ffn2 — fp16 mma: [128 slot rows] x [128 D-cols], K=1408
//           3-stage cp.async pipeline + register-fragment pipelining;
//           red.add directly into d_out.  (frozen since R7; unsplit)
// =====================================================================
#define F2_BOFF 16384
#define F2_STG  32768
#define F2_KT   (IDIM / BKH)   // 22
#define F2_SMEM (3 * F2_STG + 256)

__global__ __launch_bounds__(256, 2) void k_ffn2(float* __restrict__ out) {
    __shared__ int sTok[128];
    extern __shared__ char dynsm[];

    uint32_t raw = smem_u32(dynsm);
    uint32_t sbase = (raw + 127) & ~127u;

    const int e = blockIdx.z;
    const int cnt = g_cnt[e];
    const int m0 = blockIdx.y * 128;
    if (m0 >= cnt) return;
    const int n0 = blockIdx.x * 128;
    const int tid = threadIdx.x;

    if (tid < 128) {
        int rc = min(m0 + tid, cnt - 1);
        sTok[tid] = g_tok[e * TTOK + rc];
    }
    __syncthreads();

    const int lane = tid & 31;
    const int wid = tid >> 5;
    const int wm0 = (wid & 3) * 32;
    const int wn0 = (wid >> 2) * 64;
    const int sub = lane >> 3;
    const int l8 = lane & 7;

    const __half* hb  = g_h + (size_t)e * TTOK * IDIM;
    const __half* wdb = g_wdh + (size_t)e * DDIM * IDIM;

    const __half* aSrc[4];
    const __half* bSrc[4];
    uint32_t tDst[4];
#pragma unroll
    for (int i = 0; i < 4; i++) {
        int f = tid + i * 256;
        int row = f >> 3, c = f & 7;
        tDst[i] = row * 128 + ((c ^ (row & 7)) << 4);
        int rc = min(m0 + row, cnt - 1);
        aSrc[i] = hb + (size_t)rc * IDIM + c * 8;
        bSrc[i] = wdb + (size_t)(n0 + row) * IDIM + c * 8;
    }

    auto load_stage = [&](int st, int kt) {
        uint32_t b = sbase + st * F2_STG;
        int kb = kt * BKH;
#pragma unroll
        for (int i = 0; i < 4; i++) {
            cpa16(b + tDst[i], aSrc[i] + kb);
            cpa16(b + F2_BOFF + tDst[i], bSrc[i] + kb);
        }
    };

    uint32_t aRow[2], aXor[2];
#pragma unroll
    for (int mt = 0; mt < 2; mt++) {
        int row = wm0 + mt * 16 + ((sub & 1) << 3) + l8;
        aRow[mt] = row * 128;
        aXor[mt] = row & 7;
    }
    const uint32_t aBit = sub >> 1;
    uint32_t bRow[4], bXor[4];
#pragma unroll
    for (int p = 0; p < 4; p++) {
        int row = wn0 + p * 16 + ((sub >> 1) << 3) + l8;
        bRow[p] = row * 128;
        bXor[p] = row & 7;
    }
    const uint32_t bBit = sub & 1;

    float cc[2][8][4];
#pragma unroll
    for (int a = 0; a < 2; a++)
#pragma unroll
        for (int b = 0; b < 8; b++)
#pragma unroll
            for (int c = 0; c < 4; c++) cc[a][b][c] = 0.f;

    load_stage(0, 0);
    cpa_commit();
    load_stage(1, 1);
    cpa_commit();

    for (int kt = 0; kt < F2_KT; kt++) {
        cpa_wait<1>();
        __syncthreads();
        if (kt + 2 < F2_KT) {
            int st = (kt + 2) % 3;
            load_stage(st, kt + 2);
        }
        cpa_commit();

        uint32_t stA = sbase + (kt % 3) * F2_STG;
        uint32_t stB = stA + F2_BOFF;

        uint32_t aF[2][2][4];
        uint32_t bbF[2][4];
        ldsm_x4(aF[0][0], stA + aRow[0] + ((aBit ^ aXor[0]) << 4));
        ldsm_x4(aF[0][1], stA + aRow[1] + ((aBit ^ aXor[1]) << 4));
        ldsm_x4(bbF[0], stB + bRow[0] + ((bBit ^ bXor[0]) << 4));
#pragma unroll
        for (int g = 0; g < 4 * KSTEPS; g++) {
            const int ks = g >> 2, p = g & 3;
            const int gn = g + 1;
            if (gn < 4 * KSTEPS) {
                const int nks = gn >> 2, np = gn & 3;
                if (np == 0) {
                    uint32_t ca = (uint32_t)(nks * 2) + aBit;
                    ldsm_x4(aF[nks & 1][0], stA + aRow[0] + ((ca ^ aXor[0]) << 4));
                    ldsm_x4(aF[nks & 1][1], stA + aRow[1] + ((ca ^ aXor[1]) << 4));
                }
                uint32_t cb = (uint32_t)(nks * 2) + bBit;
                ldsm_x4(bbF[gn & 1], stB + bRow[np] + ((cb ^ bXor[np]) << 4));
            }
            const uint32_t* a0 = aF[ks & 1][0];
            const uint32_t* a1 = aF[ks & 1][1];
            const uint32_t* bb = bbF[g & 1];
            mma16816(cc[0][p * 2],     a0, bb[0], bb[1]);
            mma16816(cc[0][p * 2 + 1], a0, bb[2], bb[3]);
            mma16816(cc[1][p * 2],     a1, bb[0], bb[1]);
            mma16816(cc[1][p * 2 + 1], a1, bb[2], bb[3]);
        }
    }

#pragma unroll
    for (int mt = 0; mt < 2; mt++) {
#pragma unroll
        for (int nt = 0; nt < 8; nt++) {
            int colp = n0 + wn0 + nt * 8 + 2 * (lane & 3);
#pragma unroll
            for (int half = 0; half < 2; half++) {
                int rl = wm0 + mt * 16 + (lane >> 2) + half * 8;
                if (m0 + rl < cnt) {
                    int tok = sTok[rl];
                    float* p = out + (size_t)tok * DDIM + colp;
                    red_add_f32(p,     cc[mt][nt][half * 2]);
                    red_add_f32(p + 1, cc[mt][nt][half * 2 + 1]);
                }
            }
        }
    }
}

// ---------------- launch: expert-halved cvt -> ffn1 pipelining ----------------
extern "C" void kernel_launch(void* const* d_in, const int* in_sizes, int n_in,
                              void* d_out, int out_size) {
    const float* x  = (const float*)d_in[0];
    const float* gw = (const float*)d_in[1];
    const float* wg = (const float*)d_in[2];
    const float* wu = (const float*)d_in[3];
    const float* wd = (const float*)d_in[4];

    static cudaStream_t s1 = nullptr, s2 = nullptr, s3 = nullptr;
    static cudaEvent_t evRoot = nullptr, evA = nullptr, evB = nullptr,
                       evRtr = nullptr, evF1B = nullptr, ev2 = nullptr;
    if (s1 == nullptr) {
        cudaStreamCreateWithFlags(&s1, cudaStreamNonBlocking);
        cudaStreamCreateWithFlags(&s2, cudaStreamNonBlocking);
        cudaStreamCreateWithFlags(&s3, cudaStreamNonBlocking);
        cudaEventCreateWithFlags(&evRoot, cudaEventDisableTiming);
        cudaEventCreateWithFlags(&evA, cudaEventDisableTiming);
        cudaEventCreateWithFlags(&evB, cudaEventDisableTiming);
        cudaEventCreateWithFlags(&evRtr, cudaEventDisableTiming);
        cudaEventCreateWithFlags(&evF1B, cudaEventDisableTiming);
        cudaEventCreateWithFlags(&ev2, cudaEventDisableTiming);
        cudaFuncSetAttribute(k_ffn1, cudaFuncAttributeMaxDynamicSharedMemorySize, F1_SMEM);
        cudaFuncSetAttribute(k_ffn2, cudaFuncAttributeMaxDynamicSharedMemorySize, F2_SMEM);
    }

    const int n4w  = (int)((size_t)ENUM * IDIM * DDIM / 4);      // full tensor in float4
    const int n4h  = n4w / 2;                                    // expert half
    const size_t offF  = (size_t)n4h * 4;                        // float offset of half
    const size_t offH2 = (size_t)n4h * 2;                        // __half2 offset of half

    __half* wgh; cudaGetSymbolAddress((void**)&wgh, g_wgh);
    __half* wuh; cudaGetSymbolAddress((void**)&wuh, g_wuh);
    __half* wdh; cudaGetSymbolAddress((void**)&wdh, g_wdh);
    int* cntp;   cudaGetSymbolAddress((void**)&cntp, g_cnt);

    // fork point
    cudaEventRecord(evRoot, 0);

    // s1: convert expert half A (experts 0-3) of wg+wu  -> gates ffn1_A
    cudaStreamWaitEvent(s1, evRoot, 0);
    dim3 gCH((n4h + 1023) / 1024, 2);
    k_cvt_gu<<<gCH, 256, 0, s1>>>((const float4*)wg, (const float4*)wu,
                                  (__half2*)wgh, (__half2*)wuh, n4h);
    cudaEventRecord(evA, s1);

    // s3: convert expert half B (experts 4-7), then run ffn1_B on s3
    cudaStreamWaitEvent(s3, evRoot, 0);
    k_cvt_gu<<<gCH, 256, 0, s3>>>((const float4*)(wg + offF), (const float4*)(wu + offF),
                                  (__half2*)wgh + offH2, (__half2*)wuh + offH2, n4h);
    cudaEventRecord(evB, s3);

    // main: counter zero (memset node) + router
    cudaMemsetAsync(cntp, 0, ENUM * sizeof(int), 0);
    k_router<<<TTOK / 8, 256>>>(x, gw);
    cudaEventRecord(evRtr, 0);

    // main: ffn1_A (experts 0-3) after cvt half A
    cudaStreamWaitEvent(0, evA, 0);
    dim3 gA4(IDIM / 64, TTOK / 128, ENUM / 2);   // (22, 32, 4)
    k_ffn1<<<gA4, 256, F1_SMEM>>>(0);

    // s3: ffn1_B (experts 4-7) after router (cvt half B is in-order on s3)
    cudaStreamWaitEvent(s3, evRtr, 0);
    k_ffn1<<<gA4, 256, F1_SMEM, s3>>>(ENUM / 2);
    cudaEventRecord(evF1B, s3);

    // s2: convert wd + zero d_out, deferred behind both weight cvts
    cudaStreamWaitEvent(s2, evB, 0);
    k_cvt_one<<<(n4w + 1023) / 1024, 256, 0, s2>>>((const float4*)wd, (__half2*)wdh, n4w);
    k_zero_dout<<<(TTOK * DDIM / 4) / 256, 256, 0, s2>>>((float4*)d_out);
    cudaEventRecord(ev2, s2);

    // main: ffn2 (all experts) after ffn1_A (in-order), ffn1_B, and s2
    cudaStreamWaitEvent(0, evF1B, 0);
    cudaStreamWaitEvent(0, ev2, 0);
    dim3 gB(DDIM / 128, TTOK / 128, ENUM);  // (8, 32, 8)
    k_ffn2<<<gB, 256, F2_SMEM>>>((float*)d_out);
}